// round 3
// baseline (speedup 1.0000x reference)
#include <cuda_runtime.h>
#include <cuda_bf16.h>
#include <cstdint>

#define D_EMBED 512
#define N_CLUST 64
#define SMEM_BYTES (65536 + N_CLUST * 4 + 8 * 4)

// ---------------- device scratch (no allocations allowed) ----------------
__device__ float  g_c2[N_CLUST];
__device__ double g_acc;
__device__ __align__(16) uint2 g_bfrag[32 * 8 * 32];  // [kstep][ntile][lane] -> 2x bf16x2

// ---------------- helpers ----------------
__device__ __forceinline__ unsigned pack_bf16(float lo, float hi) {
    unsigned r;
    asm("cvt.rn.bf16x2.f32 %0, %1, %2;" : "=r"(r) : "f"(hi), "f"(lo));
    return r;
}

__device__ __forceinline__ void mma16816(float* c,
                                         unsigned a0, unsigned a1, unsigned a2, unsigned a3,
                                         unsigned b0, unsigned b1) {
    asm volatile(
        "mma.sync.aligned.m16n8k16.row.col.f32.bf16.bf16.f32 "
        "{%0,%1,%2,%3}, {%4,%5,%6,%7}, {%8,%9}, {%0,%1,%2,%3};"
        : "+f"(c[0]), "+f"(c[1]), "+f"(c[2]), "+f"(c[3])
        : "r"(a0), "r"(a1), "r"(a2), "r"(a3), "r"(b0), "r"(b1));
}

// alpha may arrive as int32 / int64 / float32 (python scalar 100). Decode robustly.
__device__ __forceinline__ float decode_alpha(const void* p) {
    int iv = *reinterpret_cast<const int*>(p);
    unsigned u = (unsigned)iv;
    unsigned ex = (u >> 23) & 0xffu;
    if (ex >= 110u && ex <= 150u) return __int_as_float(iv);  // plausible f32 ~1e-5..1e7
    if (iv == 0) {  // possible float64 scalar (low word zero)
        double dv = *reinterpret_cast<const double*>(p);
        if (dv > 1e-6 && dv < 1e9) return (float)dv;
    }
    return (float)iv;
}

// ---------------- kernel 1: c2 + zero accumulator ----------------
__global__ void prep_kernel(const float* __restrict__ cent) {
    if (blockIdx.x == 0 && threadIdx.x == 0) g_acc = 0.0;
    int w = blockIdx.x * (blockDim.x >> 5) + (threadIdx.x >> 5);
    int lane = threadIdx.x & 31;
    if (w < N_CLUST) {
        const float* c = cent + w * D_EMBED;
        float s = 0.f;
        #pragma unroll
        for (int i = 0; i < D_EMBED / 32; i++) {
            float v = c[i * 32 + lane];
            s = fmaf(v, v, s);
        }
        #pragma unroll
        for (int m = 16; m; m >>= 1) s += __shfl_xor_sync(0xffffffffu, s, m);
        if (lane == 0) g_c2[w] = s;
    }
}

// ---------------- kernel 2: centroids -> bf16 MMA B-fragment layout ----------------
// k-permutation: logical k-pairs (lo, hi) of the m16n8k16 fragment map to
// physical columns (tig*4+{0,1}) and (tig*4+{2,3}) so the A side loads float4.
__global__ void fill_kernel(const float* __restrict__ cent) {
    int id = blockIdx.x * blockDim.x + threadIdx.x;   // 0..8191
    int lane = id & 31, nt = (id >> 5) & 7, ks = id >> 8;
    int n  = nt * 8 + (lane >> 2);
    int kb = ks * 16 + (lane & 3) * 4;
    float4 v = *reinterpret_cast<const float4*>(cent + n * D_EMBED + kb);
    uint2 r;
    r.x = pack_bf16(v.x, v.y);
    r.y = pack_bf16(v.z, v.w);
    g_bfrag[id] = r;
}

// ---------------- kernel 3: main fused GEMM + softmax ----------------
__global__ __launch_bounds__(256, 2)
void main_kernel(const float* __restrict__ x, const void* __restrict__ alphap) {
    extern __shared__ unsigned char smem_raw[];
    uint2* sB  = reinterpret_cast<uint2*>(smem_raw);
    float* sc2 = reinterpret_cast<float*>(smem_raw + 65536);
    float* swp = sc2 + N_CLUST;

    int tid = threadIdx.x;
    {
        const uint4* src = reinterpret_cast<const uint4*>(g_bfrag);
        uint4* dst = reinterpret_cast<uint4*>(sB);
        #pragma unroll
        for (int i = 0; i < 16; i++) dst[i * 256 + tid] = src[i * 256 + tid];
        if (tid < N_CLUST) sc2[tid] = g_c2[tid];
    }
    __syncthreads();

    int warp = tid >> 5, lane = tid & 31;
    int g = lane >> 2, tig = lane & 3;
    size_t base = (size_t)blockIdx.x * 256 + (size_t)warp * 32;
    const float* xr00 = x + (base + g) * D_EMBED;        // mtile0, row g
    const float* xr01 = x + (base + g + 8) * D_EMBED;    // mtile0, row g+8
    const float* xr10 = x + (base + 16 + g) * D_EMBED;   // mtile1, row g
    const float* xr11 = x + (base + 16 + g + 8) * D_EMBED;

    float acc[2][8][4];
    #pragma unroll
    for (int m = 0; m < 2; m++)
        #pragma unroll
        for (int n = 0; n < 8; n++)
            #pragma unroll
            for (int j = 0; j < 4; j++) acc[m][n][j] = 0.f;

    float xs[4] = {0.f, 0.f, 0.f, 0.f};  // x^2 partials: [m*2+h]

    const uint2* bl = sB + lane;
    const int col0 = tig * 4;

    for (int ks = 0; ks < 32; ks++) {
        int col = ks * 16 + col0;
        float4 v00 = *reinterpret_cast<const float4*>(xr00 + col);
        float4 v01 = *reinterpret_cast<const float4*>(xr01 + col);
        float4 v10 = *reinterpret_cast<const float4*>(xr10 + col);
        float4 v11 = *reinterpret_cast<const float4*>(xr11 + col);

        xs[0] = fmaf(v00.x, v00.x, fmaf(v00.y, v00.y, fmaf(v00.z, v00.z, fmaf(v00.w, v00.w, xs[0]))));
        xs[1] = fmaf(v01.x, v01.x, fmaf(v01.y, v01.y, fmaf(v01.z, v01.z, fmaf(v01.w, v01.w, xs[1]))));
        xs[2] = fmaf(v10.x, v10.x, fmaf(v10.y, v10.y, fmaf(v10.z, v10.z, fmaf(v10.w, v10.w, xs[2]))));
        xs[3] = fmaf(v11.x, v11.x, fmaf(v11.y, v11.y, fmaf(v11.z, v11.z, fmaf(v11.w, v11.w, xs[3]))));

        unsigned a0m0 = pack_bf16(v00.x, v00.y), a2m0 = pack_bf16(v00.z, v00.w);
        unsigned a1m0 = pack_bf16(v01.x, v01.y), a3m0 = pack_bf16(v01.z, v01.w);
        unsigned a0m1 = pack_bf16(v10.x, v10.y), a2m1 = pack_bf16(v10.z, v10.w);
        unsigned a1m1 = pack_bf16(v11.x, v11.y), a3m1 = pack_bf16(v11.z, v11.w);

        const uint2* bk = bl + ks * 256;
        #pragma unroll
        for (int nt = 0; nt < 8; nt++) {
            uint2 b = bk[nt * 32];
            mma16816(acc[0][nt], a0m0, a1m0, a2m0, a3m0, b.x, b.y);
            mma16816(acc[1][nt], a0m1, a1m1, a2m1, a3m1, b.x, b.y);
        }
    }

    // complete x^2 across the 4-lane tig group (same rows)
    #pragma unroll
    for (int i = 0; i < 4; i++) {
        xs[i] += __shfl_xor_sync(0xffffffffu, xs[i], 1);
        xs[i] += __shfl_xor_sync(0xffffffffu, xs[i], 2);
    }

    float alpha = decode_alpha(alphap);

    float rowsum = 0.f;
    #pragma unroll
    for (int m = 0; m < 2; m++) {
        #pragma unroll
        for (int h = 0; h < 2; h++) {
            float x2v = xs[m * 2 + h];
            float dd[16];
            float dmin = 3.4e38f;
            #pragma unroll
            for (int nt = 0; nt < 8; nt++) {
                int n = nt * 8 + tig * 2;
                float d0 = x2v + sc2[n]     - 2.f * acc[m][nt][h * 2 + 0];
                float d1 = x2v + sc2[n + 1] - 2.f * acc[m][nt][h * 2 + 1];
                dd[nt * 2]     = d0;
                dd[nt * 2 + 1] = d1;
                dmin = fminf(dmin, fminf(d0, d1));
            }
            dmin = fminf(dmin, __shfl_xor_sync(0xffffffffu, dmin, 1));
            dmin = fminf(dmin, __shfl_xor_sync(0xffffffffu, dmin, 2));
            float se = 0.f, sw = 0.f;
            #pragma unroll
            for (int i = 0; i < 16; i++) {
                float e = __expf(alpha * (dmin - dd[i]));
                se += e;
                sw = fmaf(dd[i], e, sw);
            }
            se += __shfl_xor_sync(0xffffffffu, se, 1);
            se += __shfl_xor_sync(0xffffffffu, se, 2);
            sw += __shfl_xor_sync(0xffffffffu, sw, 1);
            sw += __shfl_xor_sync(0xffffffffu, sw, 2);
            rowsum += sw / se;  // identical in all 4 lanes of the tig group
        }
    }
    // warp total (each row value duplicated 4x across tig lanes -> scale 0.25)
    #pragma unroll
    for (int m = 16; m; m >>= 1) rowsum += __shfl_xor_sync(0xffffffffu, rowsum, m);
    if (lane == 0) swp[warp] = rowsum * 0.25f;
    __syncthreads();
    if (tid == 0) {
        float s = 0.f;
        #pragma unroll
        for (int i = 0; i < 8; i++) s += swp[i];
        atomicAdd(&g_acc, (double)s);
    }
}

// ---------------- kernel 4: finalize scalar ----------------
__global__ void finalize_kernel(float* __restrict__ out, int N) {
    out[0] = (float)(0.1 * g_acc / (double)N);
}

// ---------------- launch ----------------
extern "C" void kernel_launch(void* const* d_in, const int* in_sizes, int n_in,
                              void* d_out, int out_size) {
    const float* x    = (const float*)d_in[0];
    const float* cent = (const float*)d_in[1];
    const void*  ap   = d_in[2];
    int N = in_sizes[0] / D_EMBED;

    cudaFuncSetAttribute(main_kernel, cudaFuncAttributeMaxDynamicSharedMemorySize, SMEM_BYTES);

    prep_kernel<<<2, 1024>>>(cent);
    fill_kernel<<<32, 256>>>(cent);
    main_kernel<<<N / 256, 256, SMEM_BYTES>>>(x, ap);
    finalize_kernel<<<1, 1>>>((float*)d_out, N);
}

// round 6
// speedup vs baseline: 1.1160x; 1.1160x over previous
#include <cuda_runtime.h>
#include <cuda_bf16.h>
#include <cstdint>

#define D_EMBED 512
#define N_CLUST 64
#define SMEM_BYTES (65536 + N_CLUST * 4 + 8 * 4)

// ---------------- device scratch (no allocations allowed) ----------------
__device__ float  g_c2[N_CLUST];
__device__ double g_acc;
__device__ __align__(16) uint2 g_bfrag[32 * 8 * 32];  // [kstep][ntile][lane] -> 2x bf16x2

// ---------------- helpers ----------------
__device__ __forceinline__ unsigned pack_bf16(float lo, float hi) {
    unsigned r;
    asm("cvt.rn.bf16x2.f32 %0, %1, %2;" : "=r"(r) : "f"(hi), "f"(lo));
    return r;
}

__device__ __forceinline__ void mma16816(float* c,
                                         unsigned a0, unsigned a1, unsigned a2, unsigned a3,
                                         unsigned b0, unsigned b1) {
    asm volatile(
        "mma.sync.aligned.m16n8k16.row.col.f32.bf16.bf16.f32 "
        "{%0,%1,%2,%3}, {%4,%5,%6,%7}, {%8,%9}, {%0,%1,%2,%3};"
        : "+f"(c[0]), "+f"(c[1]), "+f"(c[2]), "+f"(c[3])
        : "r"(a0), "r"(a1), "r"(a2), "r"(a3), "r"(b0), "r"(b1));
}

// alpha may arrive as int32 / int64 / float32 (python scalar 100). Decode robustly.
__device__ __forceinline__ float decode_alpha(const void* p) {
    int iv = *reinterpret_cast<const int*>(p);
    unsigned u = (unsigned)iv;
    unsigned ex = (u >> 23) & 0xffu;
    if (ex >= 110u && ex <= 150u) return __int_as_float(iv);  // plausible f32 ~1e-5..1e7
    if (iv == 0) {  // possible float64 scalar (low word zero)
        double dv = *reinterpret_cast<const double*>(p);
        if (dv > 1e-6 && dv < 1e9) return (float)dv;
    }
    return (float)iv;
}

// ---------------- kernel 1: c2 + zero accumulator ----------------
__global__ void prep_kernel(const float* __restrict__ cent) {
    if (blockIdx.x == 0 && threadIdx.x == 0) g_acc = 0.0;
    int w = blockIdx.x * (blockDim.x >> 5) + (threadIdx.x >> 5);
    int lane = threadIdx.x & 31;
    if (w < N_CLUST) {
        const float* c = cent + w * D_EMBED;
        float s = 0.f;
        #pragma unroll
        for (int i = 0; i < D_EMBED / 32; i++) {
            float v = c[i * 32 + lane];
            s = fmaf(v, v, s);
        }
        #pragma unroll
        for (int m = 16; m; m >>= 1) s += __shfl_xor_sync(0xffffffffu, s, m);
        if (lane == 0) g_c2[w] = s;
    }
}

// ---------------- kernel 2: centroids -> bf16 MMA B-fragment layout ----------------
// k-permutation: logical k-pairs (lo, hi) of the m16n8k16 fragment map to
// physical columns (tig*4+{0,1}) and (tig*4+{2,3}) so the A side loads float4.
__global__ void fill_kernel(const float* __restrict__ cent) {
    int id = blockIdx.x * blockDim.x + threadIdx.x;   // 0..8191
    int lane = id & 31, nt = (id >> 5) & 7, ks = id >> 8;
    int n  = nt * 8 + (lane >> 2);
    int kb = ks * 16 + (lane & 3) * 4;
    float4 v = *reinterpret_cast<const float4*>(cent + n * D_EMBED + kb);
    uint2 r;
    r.x = pack_bf16(v.x, v.y);
    r.y = pack_bf16(v.z, v.w);
    g_bfrag[id] = r;
}

// ---------------- kernel 3: main fused GEMM + softmax ----------------
__global__ __launch_bounds__(256, 2)
void main_kernel(const float* __restrict__ x, const void* __restrict__ alphap) {
    extern __shared__ unsigned char smem_raw[];
    uint2* sB  = reinterpret_cast<uint2*>(smem_raw);
    float* sc2 = reinterpret_cast<float*>(smem_raw + 65536);
    float* swp = sc2 + N_CLUST;

    int tid = threadIdx.x;
    {
        const uint4* src = reinterpret_cast<const uint4*>(g_bfrag);
        uint4* dst = reinterpret_cast<uint4*>(sB);
        #pragma unroll
        for (int i = 0; i < 16; i++) dst[i * 256 + tid] = src[i * 256 + tid];
        if (tid < N_CLUST) sc2[tid] = g_c2[tid];
    }
    __syncthreads();

    int warp = tid >> 5, lane = tid & 31;
    int g = lane >> 2, tig = lane & 3;
    size_t base = (size_t)blockIdx.x * 256 + (size_t)warp * 32;
    const float* xr00 = x + (base + g) * D_EMBED;        // mtile0, row g
    const float* xr01 = x + (base + g + 8) * D_EMBED;    // mtile0, row g+8
    const float* xr10 = x + (base + 16 + g) * D_EMBED;   // mtile1, row g
    const float* xr11 = x + (base + 16 + g + 8) * D_EMBED;

    float acc[2][8][4];
    #pragma unroll
    for (int m = 0; m < 2; m++)
        #pragma unroll
        for (int n = 0; n < 8; n++)
            #pragma unroll
            for (int j = 0; j < 4; j++) acc[m][n][j] = 0.f;

    float xs[4] = {0.f, 0.f, 0.f, 0.f};  // x^2 partials: [m*2+h]

    const uint2* bl = sB + lane;
    const int col0 = tig * 4;

    // -------- software-pipelined mainloop: prefetch ks+1 before consuming ks --------
    float4 c00 = *reinterpret_cast<const float4*>(xr00 + col0);
    float4 c01 = *reinterpret_cast<const float4*>(xr01 + col0);
    float4 c10 = *reinterpret_cast<const float4*>(xr10 + col0);
    float4 c11 = *reinterpret_cast<const float4*>(xr11 + col0);

    for (int ks = 0; ks < 32; ks++) {
        float4 n00, n01, n10, n11;
        if (ks < 31) {
            int col = (ks + 1) * 16 + col0;
            n00 = *reinterpret_cast<const float4*>(xr00 + col);
            n01 = *reinterpret_cast<const float4*>(xr01 + col);
            n10 = *reinterpret_cast<const float4*>(xr10 + col);
            n11 = *reinterpret_cast<const float4*>(xr11 + col);
        }

        xs[0] = fmaf(c00.x, c00.x, fmaf(c00.y, c00.y, fmaf(c00.z, c00.z, fmaf(c00.w, c00.w, xs[0]))));
        xs[1] = fmaf(c01.x, c01.x, fmaf(c01.y, c01.y, fmaf(c01.z, c01.z, fmaf(c01.w, c01.w, xs[1]))));
        xs[2] = fmaf(c10.x, c10.x, fmaf(c10.y, c10.y, fmaf(c10.z, c10.z, fmaf(c10.w, c10.w, xs[2]))));
        xs[3] = fmaf(c11.x, c11.x, fmaf(c11.y, c11.y, fmaf(c11.z, c11.z, fmaf(c11.w, c11.w, xs[3]))));

        unsigned a0m0 = pack_bf16(c00.x, c00.y), a2m0 = pack_bf16(c00.z, c00.w);
        unsigned a1m0 = pack_bf16(c01.x, c01.y), a3m0 = pack_bf16(c01.z, c01.w);
        unsigned a0m1 = pack_bf16(c10.x, c10.y), a2m1 = pack_bf16(c10.z, c10.w);
        unsigned a1m1 = pack_bf16(c11.x, c11.y), a3m1 = pack_bf16(c11.z, c11.w);

        const uint2* bk = bl + ks * 256;
        #pragma unroll
        for (int nt = 0; nt < 8; nt++) {
            uint2 b = bk[nt * 32];
            mma16816(acc[0][nt], a0m0, a1m0, a2m0, a3m0, b.x, b.y);
            mma16816(acc[1][nt], a0m1, a1m1, a2m1, a3m1, b.x, b.y);
        }

        c00 = n00; c01 = n01; c10 = n10; c11 = n11;
    }

    // complete x^2 across the 4-lane tig group (same rows)
    #pragma unroll
    for (int i = 0; i < 4; i++) {
        xs[i] += __shfl_xor_sync(0xffffffffu, xs[i], 1);
        xs[i] += __shfl_xor_sync(0xffffffffu, xs[i], 2);
    }

    float alpha = decode_alpha(alphap);

    // softmax is shift-invariant in x^2: soft = softmax(-alpha * (c2 - 2*cross)),
    // and sum(dist*soft) = x2 + sum(t*soft) with t = c2 - 2*cross (since sum soft = 1).
    float rowsum = 0.f;
    #pragma unroll
    for (int m = 0; m < 2; m++) {
        #pragma unroll
        for (int h = 0; h < 2; h++) {
            float dd[16];
            float tmin = 3.4e38f;
            #pragma unroll
            for (int nt = 0; nt < 8; nt++) {
                int n = nt * 8 + tig * 2;
                float t0 = sc2[n]     - 2.f * acc[m][nt][h * 2 + 0];
                float t1 = sc2[n + 1] - 2.f * acc[m][nt][h * 2 + 1];
                dd[nt * 2]     = t0;
                dd[nt * 2 + 1] = t1;
                tmin = fminf(tmin, fminf(t0, t1));
            }
            tmin = fminf(tmin, __shfl_xor_sync(0xffffffffu, tmin, 1));
            tmin = fminf(tmin, __shfl_xor_sync(0xffffffffu, tmin, 2));
            float se = 0.f, sw = 0.f;
            #pragma unroll
            for (int i = 0; i < 16; i++) {
                float e = __expf(alpha * (tmin - dd[i]));
                se += e;
                sw = fmaf(dd[i], e, sw);
            }
            se += __shfl_xor_sync(0xffffffffu, se, 1);
            se += __shfl_xor_sync(0xffffffffu, se, 2);
            sw += __shfl_xor_sync(0xffffffffu, sw, 1);
            sw += __shfl_xor_sync(0xffffffffu, sw, 2);
            rowsum += xs[m * 2 + h] + sw / se;  // identical in all 4 tig lanes
        }
    }
    // warp total (each row value duplicated 4x across tig lanes -> scale 0.25)
    #pragma unroll
    for (int m = 16; m; m >>= 1) rowsum += __shfl_xor_sync(0xffffffffu, rowsum, m);
    if (lane == 0) swp[warp] = rowsum * 0.25f;
    __syncthreads();
    if (tid == 0) {
        float s = 0.f;
        #pragma unroll
        for (int i = 0; i < 8; i++) s += swp[i];
        atomicAdd(&g_acc, (double)s);
    }
}

// ---------------- kernel 4: finalize scalar ----------------
__global__ void finalize_kernel(float* __restrict__ out, int N) {
    out[0] = (float)(0.1 * g_acc / (double)N);
}

// ---------------- launch ----------------
extern "C" void kernel_launch(void* const* d_in, const int* in_sizes, int n_in,
                              void* d_out, int out_size) {
    const float* x    = (const float*)d_in[0];
    const float* cent = (const float*)d_in[1];
    const void*  ap   = d_in[2];
    int N = in_sizes[0] / D_EMBED;

    cudaFuncSetAttribute(main_kernel, cudaFuncAttributeMaxDynamicSharedMemorySize, SMEM_BYTES);

    prep_kernel<<<2, 1024>>>(cent);
    fill_kernel<<<32, 256>>>(cent);
    main_kernel<<<N / 256, 256, SMEM_BYTES>>>(x, ap);
    finalize_kernel<<<1, 1>>>((float*)d_out, N);
}

// round 7
// speedup vs baseline: 1.2271x; 1.0995x over previous
#include <cuda_runtime.h>
#include <cuda_bf16.h>
#include <cstdint>

#define D_EMBED 512
#define N_CLUST 64
#define X_STAGES 3
#define X_STAGE_BYTES 16384                      // 256 rows x 16 cols x 4B
#define SB_OFF (X_STAGES * X_STAGE_BYTES)        // 49152
#define SC2_OFF (SB_OFF + 65536)                 // 114688
#define SMEM_BYTES (SC2_OFF + N_CLUST * 4 + 8 * 4)

// ---------------- device scratch (no allocations allowed) ----------------
__device__ float  g_c2[N_CLUST];
__device__ double g_acc;
__device__ __align__(16) uint2 g_bfrag[32 * 8 * 32];  // [kstep][ntile][lane] -> 2x bf16x2

// ---------------- helpers ----------------
__device__ __forceinline__ unsigned pack_bf16(float lo, float hi) {
    unsigned r;
    asm("cvt.rn.bf16x2.f32 %0, %1, %2;" : "=r"(r) : "f"(hi), "f"(lo));
    return r;
}

__device__ __forceinline__ void mma16816(float* c,
                                         unsigned a0, unsigned a1, unsigned a2, unsigned a3,
                                         unsigned b0, unsigned b1) {
    asm volatile(
        "mma.sync.aligned.m16n8k16.row.col.f32.bf16.bf16.f32 "
        "{%0,%1,%2,%3}, {%4,%5,%6,%7}, {%8,%9}, {%0,%1,%2,%3};"
        : "+f"(c[0]), "+f"(c[1]), "+f"(c[2]), "+f"(c[3])
        : "r"(a0), "r"(a1), "r"(a2), "r"(a3), "r"(b0), "r"(b1));
}

__device__ __forceinline__ void cp16(unsigned dst, const float* src) {
    asm volatile("cp.async.cg.shared.global [%0], [%1], 16;" :: "r"(dst), "l"(src));
}
#define CP_COMMIT() asm volatile("cp.async.commit_group;" ::: "memory")
#define CP_WAIT2()  asm volatile("cp.async.wait_group 2;" ::: "memory")

// alpha may arrive as int32 / int64 / float32 (python scalar 100). Decode robustly.
__device__ __forceinline__ float decode_alpha(const void* p) {
    int iv = *reinterpret_cast<const int*>(p);
    unsigned u = (unsigned)iv;
    unsigned ex = (u >> 23) & 0xffu;
    if (ex >= 110u && ex <= 150u) return __int_as_float(iv);  // plausible f32 ~1e-5..1e7
    if (iv == 0) {  // possible float64 scalar (low word zero)
        double dv = *reinterpret_cast<const double*>(p);
        if (dv > 1e-6 && dv < 1e9) return (float)dv;
    }
    return (float)iv;
}

// ---------------- kernel 1: c2 + zero accumulator ----------------
__global__ void prep_kernel(const float* __restrict__ cent) {
    if (blockIdx.x == 0 && threadIdx.x == 0) g_acc = 0.0;
    int w = blockIdx.x * (blockDim.x >> 5) + (threadIdx.x >> 5);
    int lane = threadIdx.x & 31;
    if (w < N_CLUST) {
        const float* c = cent + w * D_EMBED;
        float s = 0.f;
        #pragma unroll
        for (int i = 0; i < D_EMBED / 32; i++) {
            float v = c[i * 32 + lane];
            s = fmaf(v, v, s);
        }
        #pragma unroll
        for (int m = 16; m; m >>= 1) s += __shfl_xor_sync(0xffffffffu, s, m);
        if (lane == 0) g_c2[w] = s;
    }
}

// ---------------- kernel 2: centroids -> bf16 MMA B-fragment layout ----------------
__global__ void fill_kernel(const float* __restrict__ cent) {
    int id = blockIdx.x * blockDim.x + threadIdx.x;   // 0..8191
    int lane = id & 31, nt = (id >> 5) & 7, ks = id >> 8;
    int n  = nt * 8 + (lane >> 2);
    int kb = ks * 16 + (lane & 3) * 4;
    float4 v = *reinterpret_cast<const float4*>(cent + n * D_EMBED + kb);
    uint2 r;
    r.x = pack_bf16(v.x, v.y);
    r.y = pack_bf16(v.z, v.w);
    g_bfrag[id] = r;
}

// ---------------- kernel 3: main fused GEMM + softmax ----------------
__global__ __launch_bounds__(256, 2)
void main_kernel(const float* __restrict__ x, const void* __restrict__ alphap) {
    extern __shared__ unsigned char smem_raw[];
    uint2* sB  = reinterpret_cast<uint2*>(smem_raw + SB_OFF);
    float* sc2 = reinterpret_cast<float*>(smem_raw + SC2_OFF);
    float* swp = sc2 + N_CLUST;

    int tid = threadIdx.x;
    {
        const uint4* src = reinterpret_cast<const uint4*>(g_bfrag);
        uint4* dst = reinterpret_cast<uint4*>(sB);
        #pragma unroll
        for (int i = 0; i < 16; i++) dst[i * 256 + tid] = src[i * 256 + tid];
        if (tid < N_CLUST) sc2[tid] = g_c2[tid];
    }
    __syncthreads();

    int warp = tid >> 5, lane = tid & 31;
    int g = lane >> 2, tig = lane & 3;
    size_t base = (size_t)blockIdx.x * 256 + (size_t)warp * 32;
    // lane's gmem stream: row (base + g [+8/+16/+24]), cols tig*4 + ks*16
    const float* xr = x + (base + g) * D_EMBED + tig * 4;

    // per-warp private smem x slots: [stage][warp][load j][lane] 16B each
    unsigned sx_lane;
    {
        unsigned sbase;
        asm("{ .reg .u64 t; cvta.to.shared.u64 t, %1; cvt.u32.u64 %0, t; }"
            : "=r"(sbase) : "l"(smem_raw));
        sx_lane = sbase + warp * 2048 + lane * 16;
    }

    float acc[2][8][4];
    #pragma unroll
    for (int m = 0; m < 2; m++)
        #pragma unroll
        for (int n = 0; n < 8; n++)
            #pragma unroll
            for (int j = 0; j < 4; j++) acc[m][n][j] = 0.f;

    float xs[4] = {0.f, 0.f, 0.f, 0.f};  // x^2 partials: [m*2+h]

    const uint2* bl = sB + lane;

    // ---- prologue: stage ks=0 and ks=1 ----
    #pragma unroll
    for (int p = 0; p < 2; p++) {
        unsigned d = sx_lane + p * X_STAGE_BYTES;
        const float* s = xr + p * 16;
        cp16(d,        s);                 // rows base+g
        cp16(d + 512,  s + 8  * D_EMBED);  // rows base+g+8
        cp16(d + 1024, s + 16 * D_EMBED);  // rows base+g+16
        cp16(d + 1536, s + 24 * D_EMBED);  // rows base+g+24
        CP_COMMIT();
    }

    for (int ks = 0; ks < 32; ks++) {
        // issue loads for ks+2 (empty commit in tail keeps wait_group exact)
        if (ks < 30) {
            unsigned d = sx_lane + ((ks + 2) % X_STAGES) * X_STAGE_BYTES;
            const float* s = xr + (ks + 2) * 16;
            cp16(d,        s);
            cp16(d + 512,  s + 8  * D_EMBED);
            cp16(d + 1024, s + 16 * D_EMBED);
            cp16(d + 1536, s + 24 * D_EMBED);
        }
        CP_COMMIT();
        CP_WAIT2();  // group for ks is complete

        unsigned sxs = sx_lane + (ks % X_STAGES) * X_STAGE_BYTES;
        float4 c00, c01, c10, c11;
        asm volatile("ld.shared.v4.f32 {%0,%1,%2,%3}, [%4];"
                     : "=f"(c00.x), "=f"(c00.y), "=f"(c00.z), "=f"(c00.w) : "r"(sxs));
        asm volatile("ld.shared.v4.f32 {%0,%1,%2,%3}, [%4];"
                     : "=f"(c01.x), "=f"(c01.y), "=f"(c01.z), "=f"(c01.w) : "r"(sxs + 512));
        asm volatile("ld.shared.v4.f32 {%0,%1,%2,%3}, [%4];"
                     : "=f"(c10.x), "=f"(c10.y), "=f"(c10.z), "=f"(c10.w) : "r"(sxs + 1024));
        asm volatile("ld.shared.v4.f32 {%0,%1,%2,%3}, [%4];"
                     : "=f"(c11.x), "=f"(c11.y), "=f"(c11.z), "=f"(c11.w) : "r"(sxs + 1536));

        xs[0] = fmaf(c00.x, c00.x, fmaf(c00.y, c00.y, fmaf(c00.z, c00.z, fmaf(c00.w, c00.w, xs[0]))));
        xs[1] = fmaf(c01.x, c01.x, fmaf(c01.y, c01.y, fmaf(c01.z, c01.z, fmaf(c01.w, c01.w, xs[1]))));
        xs[2] = fmaf(c10.x, c10.x, fmaf(c10.y, c10.y, fmaf(c10.z, c10.z, fmaf(c10.w, c10.w, xs[2]))));
        xs[3] = fmaf(c11.x, c11.x, fmaf(c11.y, c11.y, fmaf(c11.z, c11.z, fmaf(c11.w, c11.w, xs[3]))));

        unsigned a0m0 = pack_bf16(c00.x, c00.y), a2m0 = pack_bf16(c00.z, c00.w);
        unsigned a1m0 = pack_bf16(c01.x, c01.y), a3m0 = pack_bf16(c01.z, c01.w);
        unsigned a0m1 = pack_bf16(c10.x, c10.y), a2m1 = pack_bf16(c10.z, c10.w);
        unsigned a1m1 = pack_bf16(c11.x, c11.y), a3m1 = pack_bf16(c11.z, c11.w);

        const uint2* bk = bl + ks * 256;
        #pragma unroll
        for (int nt = 0; nt < 8; nt++) {
            uint2 b = bk[nt * 32];
            mma16816(acc[0][nt], a0m0, a1m0, a2m0, a3m0, b.x, b.y);
            mma16816(acc[1][nt], a0m1, a1m1, a2m1, a3m1, b.x, b.y);
        }
    }

    // complete x^2 across the 4-lane tig group (same rows)
    #pragma unroll
    for (int i = 0; i < 4; i++) {
        xs[i] += __shfl_xor_sync(0xffffffffu, xs[i], 1);
        xs[i] += __shfl_xor_sync(0xffffffffu, xs[i], 2);
    }

    float alpha = decode_alpha(alphap);

    // softmax is shift-invariant in x^2: soft = softmax(-alpha * (c2 - 2*cross)),
    // sum(dist*soft) = x2 + sum(t*soft) with t = c2 - 2*cross (sum soft = 1).
    float rowsum = 0.f;
    #pragma unroll
    for (int m = 0; m < 2; m++) {
        #pragma unroll
        for (int h = 0; h < 2; h++) {
            float dd[16];
            float tmin = 3.4e38f;
            #pragma unroll
            for (int nt = 0; nt < 8; nt++) {
                int n = nt * 8 + tig * 2;
                float t0 = sc2[n]     - 2.f * acc[m][nt][h * 2 + 0];
                float t1 = sc2[n + 1] - 2.f * acc[m][nt][h * 2 + 1];
                dd[nt * 2]     = t0;
                dd[nt * 2 + 1] = t1;
                tmin = fminf(tmin, fminf(t0, t1));
            }
            tmin = fminf(tmin, __shfl_xor_sync(0xffffffffu, tmin, 1));
            tmin = fminf(tmin, __shfl_xor_sync(0xffffffffu, tmin, 2));
            float se = 0.f, sw = 0.f;
            #pragma unroll
            for (int i = 0; i < 16; i++) {
                float e = __expf(alpha * (tmin - dd[i]));
                se += e;
                sw = fmaf(dd[i], e, sw);
            }
            se += __shfl_xor_sync(0xffffffffu, se, 1);
            se += __shfl_xor_sync(0xffffffffu, se, 2);
            sw += __shfl_xor_sync(0xffffffffu, sw, 1);
            sw += __shfl_xor_sync(0xffffffffu, sw, 2);
            rowsum += xs[m * 2 + h] + sw / se;  // identical in all 4 tig lanes
        }
    }
    // warp total (each row value duplicated 4x across tig lanes -> scale 0.25)
    #pragma unroll
    for (int m = 16; m; m >>= 1) rowsum += __shfl_xor_sync(0xffffffffu, rowsum, m);
    if (lane == 0) swp[warp] = rowsum * 0.25f;
    __syncthreads();
    if (tid == 0) {
        float s = 0.f;
        #pragma unroll
        for (int i = 0; i < 8; i++) s += swp[i];
        atomicAdd(&g_acc, (double)s);
    }
}

// ---------------- kernel 4: finalize scalar ----------------
__global__ void finalize_kernel(float* __restrict__ out, int N) {
    out[0] = (float)(0.1 * g_acc / (double)N);
}

// ---------------- launch ----------------
extern "C" void kernel_launch(void* const* d_in, const int* in_sizes, int n_in,
                              void* d_out, int out_size) {
    const float* x    = (const float*)d_in[0];
    const float* cent = (const float*)d_in[1];
    const void*  ap   = d_in[2];
    int N = in_sizes[0] / D_EMBED;

    cudaFuncSetAttribute(main_kernel, cudaFuncAttributeMaxDynamicSharedMemorySize, SMEM_BYTES);

    prep_kernel<<<2, 1024>>>(cent);
    fill_kernel<<<32, 256>>>(cent);
    main_kernel<<<N / 256, 256, SMEM_BYTES>>>(x, ap);
    finalize_kernel<<<1, 1>>>((float*)d_out, N);
}